// round 13
// baseline (speedup 1.0000x reference)
#include <cuda_runtime.h>
#include <cuda_fp16.h>
#include <cstdint>

#define K_DIM 64
#define BM 128
#define BN 64
#define NTHREADS 256
#define LDAB 40   // uint (half2) row stride for A/B smem tiles
#define LDC 68    // float row stride for C staging tile (conflict-free STS.128)
#define NB 37     // grid = 8*37 = 296 = 2 blocks/SM, one wave
#define MAX_ITEMS 100352

__device__ __half    g_item_half[(size_t)MAX_ITEMS * K_DIM];  // interleaved k-pairs
__device__ float     g_partial[1024];
__device__ unsigned  g_count = 0;

__device__ __forceinline__ int pgpos(int p) { return ((p & 3) << 1) | (p >> 2); }

__device__ __forceinline__ unsigned f2h2(float x, float y) {
    __half2 h = __floats2half2_rn(x, y);
    return *reinterpret_cast<unsigned*>(&h);
}

__device__ __forceinline__ float2 sel2(bool c, float2 a, float2 b) {
    return make_float2(c ? a.x : b.x, c ? a.y : b.y);
}

// Pre-convert item_emb fp32 -> half, k-pair interleaved per row.
__global__ void cvt_kernel(const float* __restrict__ item, int N) {
    int i = blockIdx.x * blockDim.x + threadIdx.x;
    if (i >= N * 4) return;
    int r = i >> 2, s = i & 3;
    const float4* src = (const float4*)(item + (size_t)r * K_DIM + s * 16);
    float4 f0 = src[0], f1 = src[1], f2 = src[2], f3 = src[3];
    unsigned u[8];
    u[0] = f2h2(f0.x, f0.y);
    u[2] = f2h2(f0.z, f0.w);
    u[4] = f2h2(f1.x, f1.y);
    u[6] = f2h2(f1.z, f1.w);
    u[1] = f2h2(f2.x, f2.y);
    u[3] = f2h2(f2.z, f2.w);
    u[5] = f2h2(f3.x, f3.y);
    u[7] = f2h2(f3.z, f3.w);
    uint4* dst = (uint4*)(g_item_half + (size_t)r * K_DIM + s * 16);
    dst[0] = make_uint4(u[0], u[1], u[2], u[3]);
    dst[1] = make_uint4(u[4], u[5], u[6], u[7]);
}

__global__ void __launch_bounds__(NTHREADS, 2)
mf_fused(const float* __restrict__ user_emb,
         const float* __restrict__ item_emb,
         const int*   __restrict__ uid,
         const int*   __restrict__ seq,
         float*       __restrict__ out,
         int N, int Bsz, int HIST, int ntiles)
{
    extern __shared__ unsigned smem[];
    unsigned* As = smem;                                    // 128 x 40 u
    unsigned* Bsb[2] = { smem + BM * LDAB,                  // 64 x 40 u each
                         smem + BM * LDAB + BN * LDAB };
    float* Csb[2] = { (float*)(smem + BM * LDAB + 2 * BN * LDAB),
                      (float*)(smem + BM * LDAB + 2 * BN * LDAB) + BM * LDC };

    const int t    = threadIdx.x;
    const int lane = t & 31, wid = t >> 5;
    const int m0   = blockIdx.y * BM;
    const int nb   = gridDim.x;
    const int bid  = blockIdx.y * nb + blockIdx.x;
    const int nblocks = nb * gridDim.y;

    float lsum = 0.f;

    // ---- load A once: gather user rows, convert to half2, k-pair interleaved ----
    {
        int r  = t >> 1;
        int cb = (t & 1) * 32;
        int u  = uid[m0 + r];
        const float4* src = (const float4*)(user_emb + (size_t)u * K_DIM + cb);
        #pragma unroll
        for (int j = 0; j < 8; j++) {
            float4 v = src[j];
            int p0 = (cb + 4 * j) >> 1;
            As[r * LDAB + ((p0 >> 3) << 3) + pgpos(p0 & 7)]       = f2h2(v.x, v.y);
            As[r * LDAB + (((p0+1) >> 3) << 3) + pgpos((p0+1)&7)] = f2h2(v.z, v.w);
        }
    }

    // 64-col windows: tile0 = [0,63), tile t>=1 = [64t-1, 64t+63)
    auto win_n0    = [&](int tile) { return tile == 0 ? 0 : tile * BN - 1; };
    auto win_ncols = [&](int tile) {
        int n0 = win_n0(tile);
        int w  = tile == 0 ? (BN - 1) : BN;
        return min(w, N - n0);
    };

    const unsigned bsaddr0 = (unsigned)__cvta_generic_to_shared(Bsb[0]);
    const unsigned bsaddr1 = (unsigned)__cvta_generic_to_shared(Bsb[1]);
    const unsigned csaddr0 = (unsigned)__cvta_generic_to_shared(Csb[0]);
    const unsigned csaddr1 = (unsigned)__cvta_generic_to_shared(Csb[1]);

    // cp.async B fill: 64 rows x 128B, zero-fill rows past ncols
    auto issueB = [&](int tile, int buf) {
        int n0 = win_n0(tile), ncols = win_ncols(tile);
        unsigned base = buf ? bsaddr1 : bsaddr0;
        #pragma unroll
        for (int it = 0; it < 2; it++) {
            int i = t + it * NTHREADS;
            int row = i >> 3, q8 = i & 7;
            const void* src = (const uint4*)(g_item_half + (size_t)(n0 + row) * K_DIM) + q8;
            unsigned dst = base + (unsigned)(row * LDAB + q8 * 4) * 4u;
            int sz = (row < ncols) ? 16 : 0;
            asm volatile("cp.async.cg.shared.global [%0], [%1], 16, %2;"
                         :: "r"(dst), "l"(src), "r"(sz) : "memory");
        }
        asm volatile("cp.async.commit_group;" ::: "memory");
    };

    issueB(blockIdx.x, 0);
    __syncthreads();   // A ready

    const int g  = lane >> 2, tq = lane & 3;
    const int wm = (wid >> 1) * 32;
    const int wn = (wid & 1) * 32;
    const unsigned* Abase = As + (wm + g) * LDAB + 2 * tq;

    // ---- hoist A fragments into registers (block-invariant across tiles) ----
    unsigned af[2][4][4];
    #pragma unroll
    for (int kk = 0; kk < 4; kk++)
        #pragma unroll
        for (int mi = 0; mi < 2; mi++) {
            uint2 x = *(const uint2*)(Abase + (mi * 16)     * LDAB + kk * 8);
            uint2 y = *(const uint2*)(Abase + (mi * 16 + 8) * LDAB + kk * 8);
            af[mi][kk][0] = x.x; af[mi][kk][2] = x.y;
            af[mi][kk][1] = y.x; af[mi][kk][3] = y.y;
        }

    const bool qb = tq & 1;
    const bool qc = tq & 2;
    // smem C row base for this thread's (mi,h) targets
    float* const crow_base[2] = {
        Csb[0] + (wm + g) * LDC + wn + 8 * tq,
        Csb[1] + (wm + g) * LDC + wn + 8 * tq };
    // bulk-store source for row t (threads 0-127)
    const unsigned csrc0 = csaddr0 + (unsigned)(t * LDC) * 4u;
    const unsigned csrc1 = csaddr1 + (unsigned)(t * LDC) * 4u;
    float* const growp = out + (size_t)(m0 + t) * N;   // + 64*tile at issue

    int pb = 0, cb = 0;

    for (int tile = blockIdx.x; tile < ntiles; tile += nb) {
        const int n0    = win_n0(tile);
        const int ncols = win_ncols(tile);
        const bool full = (tile > 0) && (n0 + BN <= N);

        asm volatile("cp.async.wait_group 0;" ::: "memory");
        if (t < BM)
            asm volatile("cp.async.bulk.wait_group.read 1;" ::: "memory");
        __syncthreads();   // B[pb] visible; C[cb] safe to overwrite
        int nxt = tile + nb;
        if (nxt < ntiles) issueB(nxt, pb ^ 1);

        const unsigned* Bbase = Bsb[pb] + (wn + g) * LDAB + 2 * tq;

        float acc[2][4][4] = {};
        #pragma unroll
        for (int kk = 0; kk < 4; kk++) {
            unsigned b0[4], b1[4];
            #pragma unroll
            for (int ni = 0; ni < 4; ni++) {
                uint2 z = *(const uint2*)(Bbase + (ni * 8) * LDAB + kk * 8);
                b0[ni] = z.x; b1[ni] = z.y;
            }
            #pragma unroll
            for (int mi = 0; mi < 2; mi++)
                #pragma unroll
                for (int ni = 0; ni < 4; ni++)
                    asm volatile(
                        "mma.sync.aligned.m16n8k16.row.col.f32.f16.f16.f32 "
                        "{%0,%1,%2,%3}, {%4,%5,%6,%7}, {%8,%9}, {%0,%1,%2,%3};\n"
                        : "+f"(acc[mi][ni][0]), "+f"(acc[mi][ni][1]),
                          "+f"(acc[mi][ni][2]), "+f"(acc[mi][ni][3])
                        : "r"(af[mi][kk][0]), "r"(af[mi][kk][1]),
                          "r"(af[mi][kk][2]), "r"(af[mi][kk][3]),
                          "r"(b0[ni]), "r"(b1[ni]));
        }

        // ---- epilogue: quad transpose -> 8 contiguous cols/thread ----
        #pragma unroll
        for (int mi = 0; mi < 2; mi++)
            #pragma unroll
            for (int h = 0; h < 2; h++) {
                float2 v0 = make_float2(acc[mi][0][2*h], acc[mi][0][2*h+1]);
                float2 v1 = make_float2(acc[mi][1][2*h], acc[mi][1][2*h+1]);
                float2 v2 = make_float2(acc[mi][2][2*h], acc[mi][2][2*h+1]);
                float2 v3 = make_float2(acc[mi][3][2*h], acc[mi][3][2*h+1]);
                // round 1 (xor 1)
                float2 ta = sel2(qb, v0, v1);
                float2 tb = sel2(qb, v2, v3);
                ta.x = __shfl_xor_sync(0xffffffffu, ta.x, 1);
                ta.y = __shfl_xor_sync(0xffffffffu, ta.y, 1);
                tb.x = __shfl_xor_sync(0xffffffffu, tb.x, 1);
                tb.y = __shfl_xor_sync(0xffffffffu, tb.y, 1);
                v0 = sel2(qb, ta, v0);  v1 = sel2(qb, v1, ta);
                v2 = sel2(qb, tb, v2);  v3 = sel2(qb, v3, tb);
                // round 2 (xor 2)
                float2 tc = sel2(qc, v0, v2);
                float2 td = sel2(qc, v1, v3);
                tc.x = __shfl_xor_sync(0xffffffffu, tc.x, 2);
                tc.y = __shfl_xor_sync(0xffffffffu, tc.y, 2);
                td.x = __shfl_xor_sync(0xffffffffu, td.x, 2);
                td.y = __shfl_xor_sync(0xffffffffu, td.y, 2);
                v0 = sel2(qc, tc, v0);  v2 = sel2(qc, v2, tc);
                v1 = sel2(qc, td, v1);  v3 = sel2(qc, v3, td);
                lsum += v0.x*v0.x + v0.y*v0.y + v1.x*v1.x + v1.y*v1.y
                      + v2.x*v2.x + v2.y*v2.y + v3.x*v3.x + v3.y*v3.y;
                if (full) {
                    // stage into smem C (conflict-free STS.128)
                    float* cr = crow_base[cb] + (mi * 16 + h * 8) * LDC;
                    *(float4*)cr       = make_float4(v0.x, v0.y, v1.x, v1.y);
                    *(float4*)(cr + 4) = make_float4(v2.x, v2.y, v3.x, v3.y);
                } else {
                    int lc = wn + 8 * tq;
                    int r0 = m0 + wm + mi * 16 + h * 8;
                    float* gp = out + 1 + (size_t)(r0 + g) * N + n0 + lc;
                    if (lc + 0 < ncols) __stcs(gp + 0, v0.x);
                    if (lc + 1 < ncols) __stcs(gp + 1, v0.y);
                    if (lc + 2 < ncols) __stcs(gp + 2, v1.x);
                    if (lc + 3 < ncols) __stcs(gp + 3, v1.y);
                    if (lc + 4 < ncols) __stcs(gp + 4, v2.x);
                    if (lc + 5 < ncols) __stcs(gp + 5, v2.y);
                    if (lc + 6 < ncols) __stcs(gp + 6, v3.x);
                    if (lc + 7 < ncols) __stcs(gp + 7, v3.y);
                }
            }

        if (full) {
            __syncthreads();   // C[cb] complete
            asm volatile("fence.proxy.async.shared::cta;" ::: "memory");
            if (t < BM) {
                // bulk store row t: 64 floats = 256B = 2 full 128B lines
                float* gdst = growp + (size_t)BN * tile;   // out-offset 64*tile (16B aligned)
                unsigned csrc = cb ? csrc1 : csrc0;
                asm volatile("cp.async.bulk.global.shared::cta.bulk_group [%0], [%1], 256;"
                             :: "l"(gdst), "r"(csrc) : "memory");
                asm volatile("cp.async.bulk.commit_group;" ::: "memory");
            }
            cb ^= 1;
        }
        pb ^= 1;
    }

    // drain outstanding bulk stores
    if (t < BM)
        asm volatile("cp.async.bulk.wait_group 0;" ::: "memory");

    // ---- positives: distinct (row, seq[row,h]) -> 1 - 2*dot, spread over all warps ----
    {
        int TW    = nblocks * (NTHREADS / 32);
        int Wg    = bid * (NTHREADS / 32) + wid;
        int total = Bsz * HIST;
        int chunk = (total + TW - 1) / TW;
        int pbeg = Wg * chunk, pend = min(pbeg + chunk, total);
        int cur_r = -1, s0 = -1, s1 = -1;
        float2 uv = make_float2(0.f, 0.f);
        float pl = 0.f;
        for (int p = pbeg; p < pend; p++) {
            int r = p / HIST, h = p % HIST;
            if (r != cur_r) {
                cur_r = r;
                s0 = (lane < HIST)      ? seq[r * HIST + lane]      : -1;
                s1 = (lane + 32 < HIST) ? seq[r * HIST + lane + 32] : -1;
                int u = uid[r];
                uv = *(const float2*)(user_emb + (size_t)u * K_DIM + 2 * lane);
            }
            int sh = (h < 32) ? __shfl_sync(0xffffffffu, s0, h)
                              : __shfl_sync(0xffffffffu, s1, h - 32);
            unsigned d0 = __ballot_sync(0xffffffffu, lane < h && s0 == sh);
            unsigned d1 = __ballot_sync(0xffffffffu, (lane + 32) < h && s1 == sh);
            if ((d0 | d1) == 0) {   // first occurrence
                float2 iv = *(const float2*)(item_emb + (size_t)sh * K_DIM + 2 * lane);
                float d = uv.x * iv.x + uv.y * iv.y;
                #pragma unroll
                for (int o = 16; o; o >>= 1) d += __shfl_xor_sync(0xffffffffu, d, o);
                pl += 1.0f - 2.0f * d;
            }
        }
        if (lane == 0) lsum += pl;
    }

    // ---- block reduce -> g_partial; last block folds everything into out[0] ----
    #pragma unroll
    for (int o = 16; o; o >>= 1) lsum += __shfl_xor_sync(0xffffffffu, lsum, o);
    __shared__ float wls[NTHREADS / 32];
    __shared__ int lastflag;
    if (lane == 0) wls[wid] = lsum;
    __syncthreads();
    if (t == 0) {
        float s = 0.f;
        #pragma unroll
        for (int i = 0; i < NTHREADS / 32; i++) s += wls[i];
        g_partial[bid] = s;
        __threadfence();
        unsigned tk = atomicAdd(&g_count, 1u);
        lastflag = (tk == (unsigned)(nblocks - 1));
    }
    __syncthreads();
    if (lastflag) {
        __threadfence();
        volatile float* gpart = g_partial;
        float s = 0.f;
        for (int i = t; i < nblocks; i += NTHREADS) s += gpart[i];
        #pragma unroll
        for (int o = 16; o; o >>= 1) s += __shfl_xor_sync(0xffffffffu, s, o);
        if (lane == 0) wls[wid] = s;
        __syncthreads();
        if (t == 0) {
            float tot = 0.f;
            #pragma unroll
            for (int i = 0; i < NTHREADS / 32; i++) tot += wls[i];
            out[0] = tot;
            g_count = 0;   // reset for next graph replay
        }
    }
}

extern "C" void kernel_launch(void* const* d_in, const int* in_sizes, int n_in,
                              void* d_out, int out_size) {
    const float* user_emb = (const float*)d_in[0];
    const float* item_emb = (const float*)d_in[1];
    const int*   uid      = (const int*)d_in[2];
    const int*   seq      = (const int*)d_in[3];
    float* out = (float*)d_out;

    int Bsz    = in_sizes[2];
    int N      = in_sizes[1] / K_DIM;
    int HIST   = in_sizes[3] / Bsz;
    // 64-col aligned windows: tile0 = 63 cols, tile t>=1 = [64t-1, 64t+63)
    int ntiles = (N <= BN - 1) ? 1 : (1 + N / BN);
    int mtiles = Bsz / BM;

    size_t smem_bytes = (size_t)(BM * LDAB + 2 * BN * LDAB) * 4
                      + (size_t)(2 * BM * LDC) * 4;
    cudaFuncSetAttribute(mf_fused, cudaFuncAttributeMaxDynamicSharedMemorySize,
                         (int)smem_bytes);

    cvt_kernel<<<(N * 4 + 255) / 256, 256>>>(item_emb, N);

    dim3 grid(NB, mtiles);
    mf_fused<<<grid, NTHREADS, smem_bytes>>>(user_emb, item_emb, uid, seq, out,
                                             N, Bsz, HIST, ntiles);
}